// round 1
// baseline (speedup 1.0000x reference)
#include <cuda_runtime.h>
#include <cstdint>

#define BATCH 16
#define CIN   128
#define HI    128
#define WIN   128
#define HO    64
#define WO    64

// ---------------- scratch (device globals; no allocation) ----------------
__device__ float g_pooled[BATCH * CIN * HO * WO];          // 33.5 MB
__device__ uint4 g_xpack[2 * BATCH * HO * WO];             // 2 branches x 128-bit/pixel = 2 MB
__device__ uint4 g_wpack[2 * 128 * 9];                     // sign bits per (branch, o, tap)
__device__ int   g_wsum [2 * 128 * 9];                     // sum of sign weights per tap
__device__ float g_scale[2 * 128];                         // mean |W| per output channel

// ---------------- kernel 1: weight prep ----------------
// one block per (branch, o); 128 threads = input channels
__global__ void wprep_kernel(const float* __restrict__ W1, const float* __restrict__ W2) {
    int bid = blockIdx.x;
    int br = bid >> 7, o = bid & 127;
    const float* W = br ? W2 : W1;
    int i = threadIdx.x;

    float w[9];
    float asum = 0.f;
#pragma unroll
    for (int t = 0; t < 9; ++t) {
        w[t] = W[(o * 128 + i) * 9 + t];
        asum += fabsf(w[t]);
    }

    __shared__ float red[128];
    red[i] = asum;
    __syncthreads();
    for (int s = 64; s > 0; s >>= 1) {
        if (i < s) red[i] += red[i + s];
        __syncthreads();
    }

    __shared__ __align__(16) unsigned wb[9][4];
    int lane = i & 31, wid = i >> 5;
#pragma unroll
    for (int t = 0; t < 9; ++t) {
        unsigned m = __ballot_sync(0xffffffffu, w[t] > 0.f);
        if (lane == 0) wb[t][wid] = m;
    }
    __syncthreads();

    if (i < 9) {
        uint4 v = *reinterpret_cast<uint4*>(wb[i]);
        g_wpack[(br * 128 + o) * 9 + i] = v;
        int ones = __popc(v.x) + __popc(v.y) + __popc(v.z) + __popc(v.w);
        g_wsum[(br * 128 + o) * 9 + i] = 2 * ones - 128;
    }
    if (i == 0) g_scale[br * 128 + o] = red[0] * (1.0f / 1152.0f);
}

// ---------------- kernel 2: 2x2 average pool ----------------
__global__ void pool_kernel(const float* __restrict__ x) {
    int idx = blockIdx.x * blockDim.x + threadIdx.x;
    if (idx >= BATCH * CIN * HO * WO) return;
    int xo = idx & 63;
    int yo = (idx >> 6) & 63;
    int cb = idx >> 12;                       // b*128 + c
    const float2* p = reinterpret_cast<const float2*>(x);
    int base = (cb * HI + 2 * yo) * (WIN / 2) + xo;
    float2 r0 = p[base];
    float2 r1 = p[base + WIN / 2];
    g_pooled[idx] = 0.25f * ((r0.x + r0.y) + (r1.x + r1.y));
}

// ---------------- kernel 3: binarize + bit-pack (both branches) ----------------
// blockDim (32,8); block covers 32 x-pixels at one (b, y)
__global__ void pack_kernel(const float* __restrict__ mvk1, const float* __restrict__ mvb1,
                            const float* __restrict__ mvk2, const float* __restrict__ mvb2) {
    __shared__ unsigned words[2][32][4];
    int tx = threadIdx.x, ty = threadIdx.y;
    int tid = ty * 32 + tx;
    // init 256 words
    reinterpret_cast<unsigned*>(words)[tid] = 0u;
    __syncthreads();

    int b = blockIdx.z, y = blockIdx.y, x0 = blockIdx.x * 32;
#pragma unroll
    for (int i = 0; i < 16; ++i) {
        int c = ty + i * 8;                                   // warp-uniform channel
        float v = g_pooled[((b * CIN + c) * HO + y) * WO + x0 + tx];
        unsigned bit = 1u << (c & 31);
        if (v * mvk1[c] + mvb1[c] > 0.f) atomicOr(&words[0][tx][c >> 5], bit);
        if (v * mvk2[c] + mvb2[c] > 0.f) atomicOr(&words[1][tx][c >> 5], bit);
    }
    __syncthreads();

    // write out 256 words
    int br = tid >> 7;
    int rem = tid & 127;
    int px = rem >> 2, w = rem & 3;
    reinterpret_cast<unsigned*>(g_xpack)[(((br * BATCH + b) * HO + y) * WO + x0 + px) * 4 + w] =
        words[br][px][w];
}

// ---------------- kernel 4: XNOR-popcount conv + RPReLU + skip + concat ----------------
// grid (8,8,16); 256 threads; thread = 1 pixel of 8x8 tile x 64 concat channels
__global__ __launch_bounds__(256) void conv_kernel(
    const float* __restrict__ pb0_1, const float* __restrict__ alpha1, const float* __restrict__ pb1_1,
    const float* __restrict__ pb0_2, const float* __restrict__ alpha2, const float* __restrict__ pb1_2,
    float* __restrict__ out) {

    __shared__ uint4 w_s[2 * 128 * 9];       // 36864 B
    __shared__ short wsum_s[2 * 128 * 9];    //  4608 B
    __shared__ float scale_s[256], pb0_s[256], alpha_s[256], pb1_s[256];  // 4096 B
    __shared__ uint4 tile[2][100];           //  3200 B  (10x10 halo per branch)

    int tid = threadIdx.x;
    int b = blockIdx.z, ty = blockIdx.y, tx = blockIdx.x;

    for (int k = tid; k < 2304; k += 256) {
        w_s[k] = g_wpack[k];
        wsum_s[k] = (short)g_wsum[k];
    }
    scale_s[tid] = g_scale[tid];
    pb0_s[tid]   = (tid < 128) ? pb0_1[tid]   : pb0_2[tid - 128];
    alpha_s[tid] = (tid < 128) ? alpha1[tid]  : alpha2[tid - 128];
    pb1_s[tid]   = (tid < 128) ? pb1_1[tid]   : pb1_2[tid - 128];

    for (int k = tid; k < 200; k += 256) {
        int br = k / 100, e = k % 100;
        int r = e / 10, cc = e % 10;
        int gy = ty * 8 - 1 + r, gx = tx * 8 - 1 + cc;
        uint4 v = make_uint4(0, 0, 0, 0);
        if (gy >= 0 && gy < 64 && gx >= 0 && gx < 64)
            v = g_xpack[((br * BATCH + b) * HO + gy) * WO + gx];
        tile[br][e] = v;
    }
    __syncthreads();

    int p = tid & 63, chunk = tid >> 6;
    int py = p >> 3, px = p & 7;
    int br = chunk >> 1;
    int gy = ty * 8 + py, gx = tx * 8 + px;

    uint4 in[9];
    int padmask = 0;
#pragma unroll
    for (int t = 0; t < 9; ++t) {
        int dy = t / 3 - 1, dx = t % 3 - 1;
        in[t] = tile[br][(py + 1 + dy) * 10 + (px + 1 + dx)];
        if (gy + dy < 0 || gy + dy > 63 || gx + dx < 0 || gx + dx > 63) padmask |= 1 << t;
    }

    const float* pooled_p = &g_pooled[(b * CIN * HO + gy) * WO + gx];
    float* out_p = &out[(b * 256 * HO + gy) * WO + gx];

#pragma unroll 2
    for (int j = 0; j < 64; ++j) {
        int oc = (chunk << 6) + j;                 // concat channel 0..255 == br*128 + o
        const uint4* wp = &w_s[oc * 9];
        int miss = 0;
#pragma unroll
        for (int t = 0; t < 9; ++t) {
            uint4 w = wp[t];
            miss += __popc(in[t].x ^ w.x) + __popc(in[t].y ^ w.y)
                  + __popc(in[t].z ^ w.z) + __popc(in[t].w ^ w.w);
        }
        int S = 1152 - 2 * miss;
        if (padmask) {
#pragma unroll
            for (int t = 0; t < 9; ++t)
                if (padmask & (1 << t)) S += (int)wsum_s[oc * 9 + t];
        }
        float yv = scale_s[oc] * (float)S + pb0_s[oc];
        yv = (yv >= 0.f) ? yv : alpha_s[oc] * yv;
        yv += pb1_s[oc];
        int o = oc & 127;
        out_p[oc * (HO * WO)] = pooled_p[o * (HO * WO)] + yv;
    }
}

// ---------------- launch ----------------
extern "C" void kernel_launch(void* const* d_in, const int* in_sizes, int n_in,
                              void* d_out, int out_size) {
    const float* x      = (const float*)d_in[0];
    const float* W1     = (const float*)d_in[1];
    const float* mvk1   = (const float*)d_in[2];
    const float* mvb1   = (const float*)d_in[3];
    // d_in[4] = beta1 (forward value is sign(); beta only affects gradients)
    const float* pb0_1  = (const float*)d_in[5];
    const float* alpha1 = (const float*)d_in[6];
    const float* pb1_1  = (const float*)d_in[7];
    const float* W2     = (const float*)d_in[8];
    const float* mvk2   = (const float*)d_in[9];
    const float* mvb2   = (const float*)d_in[10];
    // d_in[11] = beta2
    const float* pb0_2  = (const float*)d_in[12];
    const float* alpha2 = (const float*)d_in[13];
    const float* pb1_2  = (const float*)d_in[14];
    float* out = (float*)d_out;

    wprep_kernel<<<256, 128>>>(W1, W2);
    pool_kernel<<<(BATCH * CIN * HO * WO) / 256, 256>>>(x);
    pack_kernel<<<dim3(2, 64, 16), dim3(32, 8)>>>(mvk1, mvb1, mvk2, mvb2);
    conv_kernel<<<dim3(8, 8, 16), 256>>>(pb0_1, alpha1, pb1_1, pb0_2, alpha2, pb1_2, out);
}

// round 2
// speedup vs baseline: 1.1334x; 1.1334x over previous
#include <cuda_runtime.h>
#include <cstdint>

#define BATCH 16
#define CIN   128
#define HI    128
#define WIN   128
#define HO    64
#define WO    64

// ---------------- scratch (device globals; no allocation) ----------------
__device__ float g_pooled[BATCH * CIN * HO * WO];          // 33.5 MB
__device__ uint4 g_xpack[2 * BATCH * HO * WO];             // 2 branches x 128-bit/pixel = 2 MB
__device__ uint4 g_wpack[2 * 128 * 9];                     // sign bits per (branch, o, tap)
__device__ int   g_wsum [2 * 128 * 9];                     // sum of sign weights per tap
__device__ float g_scale[2 * 128];                         // mean |W| per output channel

// ---------------- kernel 1: weight prep ----------------
// one block per (branch, o); 128 threads = input channels
__global__ void wprep_kernel(const float* __restrict__ W1, const float* __restrict__ W2) {
    int bid = blockIdx.x;
    int br = bid >> 7, o = bid & 127;
    const float* W = br ? W2 : W1;
    int i = threadIdx.x;

    float w[9];
    float asum = 0.f;
#pragma unroll
    for (int t = 0; t < 9; ++t) {
        w[t] = W[(o * 128 + i) * 9 + t];
        asum += fabsf(w[t]);
    }

    __shared__ float red[128];
    red[i] = asum;
    __syncthreads();
    for (int s = 64; s > 0; s >>= 1) {
        if (i < s) red[i] += red[i + s];
        __syncthreads();
    }

    __shared__ __align__(16) unsigned wb[9][4];
    int lane = i & 31, wid = i >> 5;
#pragma unroll
    for (int t = 0; t < 9; ++t) {
        unsigned m = __ballot_sync(0xffffffffu, w[t] > 0.f);
        if (lane == 0) wb[t][wid] = m;
    }
    __syncthreads();

    if (i < 9) {
        uint4 v = *reinterpret_cast<uint4*>(wb[i]);
        g_wpack[(br * 128 + o) * 9 + i] = v;
        int ones = __popc(v.x) + __popc(v.y) + __popc(v.z) + __popc(v.w);
        g_wsum[(br * 128 + o) * 9 + i] = 2 * ones - 128;
    }
    if (i == 0) g_scale[br * 128 + o] = red[0] * (1.0f / 1152.0f);
}

// ---------------- kernel 2: fused 2x2 avg pool + binarize + bit-pack ----------------
// block (32,8); covers 32 x-pixels at one (b, y); reads x once, writes pooled + both bitplanes
__global__ void poolpack_kernel(const float* __restrict__ x,
                                const float* __restrict__ mvk1, const float* __restrict__ mvb1,
                                const float* __restrict__ mvk2, const float* __restrict__ mvb2) {
    __shared__ unsigned words[2][32][4];
    int tx = threadIdx.x, ty = threadIdx.y;
    int tid = ty * 32 + tx;
    reinterpret_cast<unsigned*>(words)[tid] = 0u;
    __syncthreads();

    int b = blockIdx.z, y = blockIdx.y, x0 = blockIdx.x * 32;
    int xo = x0 + tx;
    const float2* p = reinterpret_cast<const float2*>(x);

#pragma unroll
    for (int i = 0; i < 16; ++i) {
        int c = ty + i * 8;                                   // warp-uniform channel
        int base = ((b * CIN + c) * HI + 2 * y) * (WIN / 2) + xo;
        float2 r0 = p[base];
        float2 r1 = p[base + WIN / 2];
        float v = 0.25f * ((r0.x + r0.y) + (r1.x + r1.y));
        g_pooled[((b * CIN + c) * HO + y) * WO + xo] = v;
        unsigned bit = 1u << (c & 31);
        if (v * mvk1[c] + mvb1[c] > 0.f) atomicOr(&words[0][tx][c >> 5], bit);
        if (v * mvk2[c] + mvb2[c] > 0.f) atomicOr(&words[1][tx][c >> 5], bit);
    }
    __syncthreads();

    int br = tid >> 7;
    int rem = tid & 127;
    int px = rem >> 2, w = rem & 3;
    reinterpret_cast<unsigned*>(g_xpack)[(((br * BATCH + b) * HO + y) * WO + x0 + px) * 4 + w] =
        words[br][px][w];
}

// ---------------- kernel 3: XNOR-popcount conv + RPReLU + skip + concat ----------------
// grid (8,8,32); z = b*2+br; 256 threads; thread = 1 pixel x 32 output channels
__global__ __launch_bounds__(256, 4) void conv_kernel(
    const float* __restrict__ pb0_1, const float* __restrict__ alpha1, const float* __restrict__ pb1_1,
    const float* __restrict__ pb0_2, const float* __restrict__ alpha2, const float* __restrict__ pb1_2,
    float* __restrict__ out) {

    __shared__ uint4 w_s[128 * 9];           // 18432 B
    __shared__ short wsum_s[128 * 9];        //  2304 B
    __shared__ float scale_s[128], pb0_s[128], alpha_s[128], pb1_s[128];  // 2048 B
    __shared__ uint4 tile[100];              //  1600 B  (10x10 halo)

    int tid = threadIdx.x;
    int z = blockIdx.z;
    int b = z >> 1, br = z & 1;
    int ty = blockIdx.y, tx = blockIdx.x;

    for (int k = tid; k < 1152; k += 256) {
        w_s[k] = g_wpack[br * 1152 + k];
        wsum_s[k] = (short)g_wsum[br * 1152 + k];
    }
    if (tid < 128) {
        scale_s[tid] = g_scale[br * 128 + tid];
        pb0_s[tid]   = br ? pb0_2[tid]   : pb0_1[tid];
        alpha_s[tid] = br ? alpha2[tid]  : alpha1[tid];
        pb1_s[tid]   = br ? pb1_2[tid]   : pb1_1[tid];
    }
    for (int k = tid; k < 100; k += 256) {
        int r = k / 10, cc = k % 10;
        int gy = ty * 8 - 1 + r, gx = tx * 8 - 1 + cc;
        uint4 v = make_uint4(0, 0, 0, 0);
        if (gy >= 0 && gy < 64 && gx >= 0 && gx < 64)
            v = g_xpack[((br * BATCH + b) * HO + gy) * WO + gx];
        tile[k] = v;
    }
    __syncthreads();

    int p = tid & 63, chunk = tid >> 6;      // chunk warp-uniform -> weight LDS broadcast
    int py = p >> 3, px = p & 7;
    int gy = ty * 8 + py, gx = tx * 8 + px;

    uint4 in[9];
    int padmask = 0;
#pragma unroll
    for (int t = 0; t < 9; ++t) {
        int dy = t / 3 - 1, dx = t % 3 - 1;
        in[t] = tile[(py + 1 + dy) * 10 + (px + 1 + dx)];
        if (gy + dy < 0 || gy + dy > 63 || gx + dx < 0 || gx + dx > 63) padmask |= 1 << t;
    }

    const float* pooled_p = &g_pooled[(b * CIN * HO + gy) * WO + gx];
    float* out_p = &out[((b * 256 + br * 128) * HO + gy) * WO + gx];

#pragma unroll 4
    for (int j = 0; j < 32; ++j) {
        int o = (chunk << 5) + j;            // 0..127, warp-uniform
        const uint4* wp = &w_s[o * 9];
        int miss = 0;
#pragma unroll
        for (int t = 0; t < 9; ++t) {
            uint4 w = wp[t];
            miss += __popc(in[t].x ^ w.x) + __popc(in[t].y ^ w.y)
                  + __popc(in[t].z ^ w.z) + __popc(in[t].w ^ w.w);
        }
        int S = 1152 - 2 * miss;
        if (padmask) {
#pragma unroll
            for (int t = 0; t < 9; ++t)
                if (padmask & (1 << t)) S += (int)wsum_s[o * 9 + t];
        }
        float yv = scale_s[o] * (float)S + pb0_s[o];
        yv = (yv >= 0.f) ? yv : alpha_s[o] * yv;
        yv += pb1_s[o];
        out_p[o * (HO * WO)] = pooled_p[o * (HO * WO)] + yv;
    }
}

// ---------------- launch ----------------
extern "C" void kernel_launch(void* const* d_in, const int* in_sizes, int n_in,
                              void* d_out, int out_size) {
    const float* x      = (const float*)d_in[0];
    const float* W1     = (const float*)d_in[1];
    const float* mvk1   = (const float*)d_in[2];
    const float* mvb1   = (const float*)d_in[3];
    // d_in[4] = beta1 (forward value is sign(); beta only affects gradients)
    const float* pb0_1  = (const float*)d_in[5];
    const float* alpha1 = (const float*)d_in[6];
    const float* pb1_1  = (const float*)d_in[7];
    const float* W2     = (const float*)d_in[8];
    const float* mvk2   = (const float*)d_in[9];
    const float* mvb2   = (const float*)d_in[10];
    // d_in[11] = beta2
    const float* pb0_2  = (const float*)d_in[12];
    const float* alpha2 = (const float*)d_in[13];
    const float* pb1_2  = (const float*)d_in[14];
    float* out = (float*)d_out;

    wprep_kernel<<<256, 128>>>(W1, W2);
    poolpack_kernel<<<dim3(2, 64, 16), dim3(32, 8)>>>(x, mvk1, mvb1, mvk2, mvb2);
    conv_kernel<<<dim3(8, 8, BATCH * 2), 256>>>(pb0_1, alpha1, pb1_1,
                                                pb0_2, alpha2, pb1_2, out);
}